// round 8
// baseline (speedup 1.0000x reference)
#include <cuda_runtime.h>
#include <cuda_fp16.h>
#include <cstdint>

// Problem constants
#define B_   4
#define N_   4096
#define C_   128
#define H_   4
#define D_   32
#define BH_  (B_*H_)           // 16
#define QK_ELEMS (BH_*N_*D_)   // 2,097,152

// ---------------- static scratch (no allocs allowed) ----------------
__device__ __half g_Qh[QK_ELEMS];        // raw q (unnormalized) fp16
__device__ __half g_Kh[QK_ELEMS];        // raw k fp16
__device__ __half g_Vh[QK_ELEMS];
__device__ __half g_Oh[B_*N_*C_];        // attention output fp16 [b][n][h*32+d]
__device__ float  g_part[2][64][512];    // column sumsq partials [q/k][rowchunk][bh*32+d]

// ---------------- PTX helpers ----------------
#define MMA16816(d, a, b0, b1)                                                  \
    asm volatile("mma.sync.aligned.m16n8k16.row.col.f32.f16.f16.f32 "          \
        "{%0,%1,%2,%3}, {%4,%5,%6,%7}, {%8,%9}, {%0,%1,%2,%3};\n"              \
        : "+f"(d[0]), "+f"(d[1]), "+f"(d[2]), "+f"(d[3])                        \
        : "r"(a[0]), "r"(a[1]), "r"(a[2]), "r"(a[3]), "r"(b0), "r"(b1))

#define LDMX4(r0,r1,r2,r3,addr)                                                 \
    asm volatile("ldmatrix.sync.aligned.m8n8.x4.shared.b16 {%0,%1,%2,%3}, [%4];\n" \
        : "=r"(r0), "=r"(r1), "=r"(r2), "=r"(r3) : "r"(addr))

#define LDMX4T(r0,r1,r2,r3,addr)                                                \
    asm volatile("ldmatrix.sync.aligned.m8n8.x4.trans.shared.b16 {%0,%1,%2,%3}, [%4];\n" \
        : "=r"(r0), "=r"(r1), "=r"(r2), "=r"(r3) : "r"(addr))

__device__ __forceinline__ void cp16(uint32_t dst, const void* src) {
    asm volatile("cp.async.cg.shared.global [%0], [%1], 16;\n" :: "r"(dst), "l"(src));
}
#define CP_COMMIT() asm volatile("cp.async.commit_group;\n" ::: "memory")
#define CP_WAIT0()  asm volatile("cp.async.wait_group 0;\n" ::: "memory")

__device__ __forceinline__ unsigned pack_h2(float x, float y) {
    __half2 h = __float22half2_rn(make_float2(x, y));
    return *reinterpret_cast<unsigned*>(&h);
}
__device__ __forceinline__ unsigned ex2h2(unsigned x) {
    unsigned r; asm("ex2.approx.f16x2 %0, %1;" : "=r"(r) : "r"(x)); return r;
}

// convert two float4 -> int4 of 8 halves
__device__ __forceinline__ int4 cvt8r(float4 v0, float4 v1) {
    __half2 h[4];
    h[0] = __float22half2_rn(make_float2(v0.x, v0.y));
    h[1] = __float22half2_rn(make_float2(v0.z, v0.w));
    h[2] = __float22half2_rn(make_float2(v1.x, v1.y));
    h[3] = __float22half2_rn(make_float2(v1.z, v1.w));
    return *(int4*)h;
}

#define AP 136   // A smem pitch (halves), conflict-free for LDSM
#define BP 72    // B smem pitch (halves)

// =====================================================================
// Kernel 1: QKV GEMM fp16 tensor-core with A-tile reuse across all 384
// output columns + fused column-sumsq partials for q/k.
// Block: 64 rows x 384 cols. grid 256, 256 thr (8 warps: (w&3)=rowgrp,
// (w>>2)=32-col half of the 64-col nc chunk).
// =====================================================================
__global__ __launch_bounds__(256) void gemm_qkv_h(
    const float* __restrict__ X, const float* __restrict__ Wq)
{
    __shared__ __align__(16) __half As[64][AP];
    __shared__ __align__(16) __half Bs[128][BP];
    __shared__ float wsum[8][64];

    const int mt   = blockIdx.x;      // 0..255 (64 rows each)
    const int tid  = threadIdx.x;
    const int lane = tid & 31;
    const int warp = tid >> 5;
    const int wr   = (warp & 3) * 16; // row base within tile
    const int wh   = warp >> 2;       // 0/1: 32-col half
    const int g    = lane >> 2;
    const int q2   = (lane & 3) * 2;

    const uint32_t as_base = (uint32_t)__cvta_generic_to_shared(&As[0][0]);
    const uint32_t bs_base = (uint32_t)__cvta_generic_to_shared(&Bs[0][0]);

    // ---- stage A once: 64x128 fp32 -> fp16 smem ----
    {
        const int row = tid >> 2;
        const int c0  = (tid & 3) * 32;
        const float* src = X + (mt * 64 + row) * 128 + c0;
        #pragma unroll
        for (int j = 0; j < 4; j++) {
            float4 v0 = *(const float4*)(src + j * 8);
            float4 v1 = *(const float4*)(src + j * 8 + 4);
            *(int4*)&As[row][c0 + j * 8] = cvt8r(v0, v1);
        }
    }

    // ---- B prefetch registers (128x64 fp32 per nc; 32 els/thread) ----
    const int brow = tid >> 1;
    const int bc0  = (tid & 1) * 32;
    float4 f[8];
    {
        const float* src = Wq + brow * 384 + 0 * 64 + bc0;
        #pragma unroll
        for (int j = 0; j < 4; j++) {
            f[2*j]   = *(const float4*)(src + j * 8);
            f[2*j+1] = *(const float4*)(src + j * 8 + 4);
        }
    }

    const int b_batch = mt >> 6;      // batch index
    const int mtc     = mt & 63;      // row-chunk within batch (for g_part)

    #pragma unroll 1
    for (int nc = 0; nc < 6; nc++) {
        // store B(nc) to smem
        #pragma unroll
        for (int j = 0; j < 4; j++)
            *(int4*)&Bs[brow][bc0 + j * 8] = cvt8r(f[2*j], f[2*j+1]);
        __syncthreads();

        // prefetch B(nc+1)
        if (nc < 5) {
            const float* src = Wq + brow * 384 + (nc + 1) * 64 + bc0;
            #pragma unroll
            for (int j = 0; j < 4; j++) {
                f[2*j]   = *(const float4*)(src + j * 8);
                f[2*j+1] = *(const float4*)(src + j * 8 + 4);
            }
        }

        // ---- compute 16x32 per warp over K=128 ----
        float acc[4][4];
        #pragma unroll
        for (int t = 0; t < 4; t++)
            #pragma unroll
            for (int r = 0; r < 4; r++) acc[t][r] = 0.f;

        #pragma unroll
        for (int kc = 0; kc < 8; kc++) {
            unsigned a[4];
            LDMX4(a[0], a[1], a[2], a[3], as_base +
                (uint32_t)(((wr + (lane & 15)) * AP + kc * 16 + (lane >> 4) * 8) * 2));
            #pragma unroll
            for (int t = 0; t < 2; t++) {
                unsigned b0, b1, b2, b3;
                LDMX4T(b0, b1, b2, b3, bs_base +
                    (uint32_t)(((kc * 16 + (lane & 15)) * BP + wh * 32 + t * 16 + (lane >> 4) * 8) * 2));
                MMA16816(acc[2 * t],     a, b0, b1);
                MMA16816(acc[2 * t + 1], a, b2, b3);
            }
        }

        // ---- store q/k/v fp16 ----
        #pragma unroll
        for (int t = 0; t < 4; t++) {
            int e  = nc * 64 + wh * 32 + t * 8 + q2;
            int ec = e & 127;
            int h  = ec >> 5, d = ec & 31;
            #pragma unroll
            for (int half_ = 0; half_ < 2; half_++) {
                int m = mt * 64 + wr + g + half_ * 8;
                int n = m & 4095;
                int idx = ((b_batch * 4 + h) * 4096 + n) * 32 + d;
                __half2 hv = __float22half2_rn(
                    make_float2(acc[t][half_ * 2], acc[t][half_ * 2 + 1]));
                if (nc < 2)      *(__half2*)&g_Qh[idx] = hv;
                else if (nc < 4) *(__half2*)&g_Kh[idx] = hv;
                else             *(__half2*)&g_Vh[idx] = hv;
            }
        }

        // ---- fused column sumsq partials (q/k only) ----
        if (nc < 4) {
            #pragma unroll
            for (int t = 0; t < 4; t++) {
                float s0 = acc[t][0]*acc[t][0] + acc[t][2]*acc[t][2];
                float s1 = acc[t][1]*acc[t][1] + acc[t][3]*acc[t][3];
                #pragma unroll
                for (int m = 4; m < 32; m <<= 1) {
                    s0 += __shfl_xor_sync(0xffffffffu, s0, m);
                    s1 += __shfl_xor_sync(0xffffffffu, s1, m);
                }
                if (g == 0) {
                    int jloc = wh * 32 + t * 8 + q2;
                    wsum[warp][jloc]     = s0;
                    wsum[warp][jloc + 1] = s1;
                }
            }
        }
        __syncthreads();   // compute + wsum done; Bs free for next STS

        if (nc < 4 && tid < 64) {
            int h4 = tid >> 5;   // which half of the 64 cols
            float s = wsum[h4*4+0][tid] + wsum[h4*4+1][tid]
                    + wsum[h4*4+2][tid] + wsum[h4*4+3][tid];
            int e = nc * 64 + tid;
            int which = e >> 7;            // 0=q, 1=k
            int ec = e & 127;
            int h  = ec >> 5, d = ec & 31;
            g_part[which][mtc][(b_batch * 4 + h) * 32 + d] = s;
        }
    }
}

// =====================================================================
// Kernel 2: flash attention. Scale finalized in-block from g_part,
// applied at Q staging; exp via ex2.approx.f16x2; row-sum l via
// ones-MMA; 1 barrier/iter. grid (32 q-tiles of 128, 16 bh), 256 thr.
// =====================================================================
#define PITCH     40                    // halves per smem row
#define KV_BYTES  (64 * PITCH * 2)      // bytes per K or V stage

__global__ __launch_bounds__(256) void flash_kernel()
{
    const int qt   = blockIdx.x;      // 0..31
    const int bh   = blockIdx.y;      // 0..15
    const int tid  = threadIdx.x;
    const int lane = tid & 31;
    const int warp = tid >> 5;        // 0..7
    const int g    = lane >> 2;       // 0..7

    __shared__ __align__(16) __half Qs[128][PITCH];
    __shared__ __align__(16) __half Ks[2][64][PITCH];
    __shared__ __align__(16) __half Vs[2][64][PITCH];
    __shared__ float scl[32];

    const __half* Qg = g_Qh + (bh * N_ + qt * 128) * 32;
    const __half* Kg = g_Kh + bh * N_ * 32;
    const __half* Vg = g_Vh + bh * N_ * 32;

    const uint32_t qs_base = (uint32_t)__cvta_generic_to_shared(&Qs[0][0]);
    const uint32_t ks_base = (uint32_t)__cvta_generic_to_shared(&Ks[0][0][0]);
    const uint32_t vs_base = (uint32_t)__cvta_generic_to_shared(&Vs[0][0][0]);

    const int crow = tid >> 2;
    const int ccol = (tid & 3) * 8;
    const uint32_t cdst = (uint32_t)(crow * (PITCH * 2) + ccol * 2);
    const int     csrc  = crow * 32 + ccol;

    // prefetch KV tile 0
    cp16(ks_base + cdst, Kg + csrc);
    cp16(vs_base + cdst, Vg + csrc);
    CP_COMMIT();

    // per-block scale finalize from 64 partial chunks
    if (tid < 32) {
        float qs = 0.f, ks = 0.f;
        #pragma unroll
        for (int c = 0; c < 64; c++) {
            qs += g_part[0][c][bh * 32 + tid];
            ks += g_part[1][c][bh * 32 + tid];
        }
        float qn = fmaxf(sqrtf(qs), 1e-12f);
        float kn = fmaxf(sqrtf(ks), 1e-12f);
        scl[tid] = 14.4269504088896f / (qn * kn);   // 10*log2(e)/(|q||k|)
    }
    __syncthreads();

    // stage Q (raw fp16 * fp32 scale -> fp16) while tile 0 streams
    {
        const int d0 = (tid & 3) * 8;
        float sc[8];
        #pragma unroll
        for (int j = 0; j < 8; j++) sc[j] = scl[d0 + j];
        const int4* src = (const int4*)Qg;
        #pragma unroll
        for (int i = tid; i < 512; i += 256) {
            int4 v = src[i];
            __half2* hp = (__half2*)&v;
            #pragma unroll
            for (int j = 0; j < 4; j++) {
                float2 fv = __half22float2(hp[j]);
                fv.x *= sc[2 * j]; fv.y *= sc[2 * j + 1];
                hp[j] = __float22half2_rn(fv);
            }
            *(int4*)&Qs[i >> 2][(i & 3) * 8] = v;
        }
    }
    __syncthreads();

    // Q A-fragments for the whole loop
    unsigned qa[2][4];
    const int rb = warp * 16;
    #pragma unroll
    for (int kc = 0; kc < 2; kc++) {
        uint32_t addr = qs_base +
            (uint32_t)(((rb + (lane & 15)) * PITCH + kc * 16 + (lane >> 4) * 8) * 2);
        LDMX4(qa[kc][0], qa[kc][1], qa[kc][2], qa[kc][3], addr);
    }

    float o[4][4];
    #pragma unroll
    for (int t = 0; t < 4; t++)
        #pragma unroll
        for (int r = 0; r < 4; r++) o[t][r] = 0.f;
    float lacc[4] = {0.f, 0.f, 0.f, 0.f};
    const unsigned ONES = 0x3C003C00u;    // (1.0h, 1.0h)

    for (int kb = 0; kb < 64; kb++) {
        const int st = kb & 1;
        CP_WAIT0();
        __syncthreads();

        if (kb + 1 < 64) {     // prefetch next tile, overlaps compute
            uint32_t off = (uint32_t)((st ^ 1) * KV_BYTES) + cdst;
            int s2 = (kb + 1) * 64 * 32 + csrc;
            cp16(ks_base + off, Kg + s2);
            cp16(vs_base + off, Vg + s2);
            CP_COMMIT();
        }

        const uint32_t kbase = ks_base + st * KV_BYTES;
        const uint32_t vbase = vs_base + st * KV_BYTES;

        // ---- S = Q K^T (16 x 64 per warp), log2-domain logits ----
        float s[8][4];
        #pragma unroll
        for (int t = 0; t < 8; t++) {
            unsigned b0, b1, b2, b3;
            uint32_t addr = kbase +
                (uint32_t)(((t * 8 + (lane & 7)) * PITCH + (lane >> 3) * 8) * 2);
            LDMX4(b0, b1, b2, b3, addr);
            s[t][0] = s[t][1] = s[t][2] = s[t][3] = 0.f;
            MMA16816(s[t], qa[0], b0, b1);
            MMA16816(s[t], qa[1], b2, b3);
        }

        // ---- per jc-chunk: pack -> ex2.f16x2 -> l-MMA + PV MMAs ----
        #pragma unroll
        for (int jc = 0; jc < 4; jc++) {
            unsigned pu[4];
            pu[0] = ex2h2(pack_h2(s[2*jc][0],   s[2*jc][1]));
            pu[1] = ex2h2(pack_h2(s[2*jc][2],   s[2*jc][3]));
            pu[2] = ex2h2(pack_h2(s[2*jc+1][0], s[2*jc+1][1]));
            pu[3] = ex2h2(pack_h2(s[2*jc+1][2], s[2*jc+1][3]));

            MMA16816(lacc, pu, ONES, ONES);   // row sums -> persistent fp32 acc

            uint32_t a0 = vbase +
                (uint32_t)(((jc * 16 + (lane & 15)) * PITCH + (lane >> 4) * 8) * 2);
            unsigned r0, r1, r2, r3;
            LDMX4T(r0, r1, r2, r3, a0);
            MMA16816(o[0], pu, r0, r1);
            MMA16816(o[1], pu, r2, r3);
            LDMX4T(r0, r1, r2, r3, a0 + 32);
            MMA16816(o[2], pu, r0, r1);
            MMA16816(o[3], pu, r2, r3);
        }
    }

    // ---- finalize: l broadcast across accumulator columns ----
    const int q2 = (lane & 3) * 2;
    float inv0 = 1.0f / lacc[0];
    float inv1 = 1.0f / lacc[2];

    int b = bh >> 2, h = bh & 3;
    int row0 = qt * 128 + rb + g;
    __half* dst0 = g_Oh + (b * N_ + row0) * 128 + h * 32;
    __half* dst1 = dst0 + 8 * 128;
    #pragma unroll
    for (int t = 0; t < 4; t++) {
        int d = t * 8 + q2;
        *(__half2*)&dst0[d] = __float22half2_rn(make_float2(o[t][0] * inv0, o[t][1] * inv0));
        *(__half2*)&dst1[d] = __float22half2_rn(make_float2(o[t][2] * inv1, o[t][3] * inv1));
    }
}

// =====================================================================
// Kernel 3: output projection, single-pass K=128, 64x64 tiles.
// grid (2 nc, 256 mt), 256 thr (8 warps: rowgrp x 32-col half).
// =====================================================================
__global__ __launch_bounds__(256) void gemm_out_h(
    const float* __restrict__ Wo, const float* __restrict__ bias,
    float* __restrict__ out)
{
    __shared__ __align__(16) __half As[64][AP];
    __shared__ __align__(16) __half Bs[128][BP];

    const int nc   = blockIdx.x;      // 0..1
    const int mt   = blockIdx.y;      // 0..255
    const int tid  = threadIdx.x;
    const int lane = tid & 31;
    const int warp = tid >> 5;
    const int wr   = (warp & 3) * 16;
    const int wh   = warp >> 2;
    const int g    = lane >> 2;
    const int q2   = (lane & 3) * 2;

    const uint32_t as_base = (uint32_t)__cvta_generic_to_shared(&As[0][0]);
    const uint32_t bs_base = (uint32_t)__cvta_generic_to_shared(&Bs[0][0]);
    const __half* Ap = g_Oh + mt * 64 * 128;

    // A: 64x128 fp16 via cp.async (1024 16B chunks, 4/thread)
    #pragma unroll
    for (int j = 0; j < 4; j++) {
        int i = tid + j * 256;
        int row = i >> 4, c8 = (i & 15) * 8;
        cp16(as_base + (uint32_t)((row * AP + c8) * 2), Ap + row * 128 + c8);
    }
    CP_COMMIT();

    // B: 128x64 fp32 -> fp16 (32 els/thread)
    {
        const int brow = tid >> 1;
        const int bc0  = (tid & 1) * 32;
        const float* src = Wo + brow * 128 + nc * 64 + bc0;
        #pragma unroll
        for (int j = 0; j < 4; j++) {
            float4 v0 = *(const float4*)(src + j * 8);
            float4 v1 = *(const float4*)(src + j * 8 + 4);
            *(int4*)&Bs[brow][bc0 + j * 8] = cvt8r(v0, v1);
        }
    }
    CP_WAIT0();
    __syncthreads();

    float acc[4][4];
    #pragma unroll
    for (int t = 0; t < 4; t++)
        #pragma unroll
        for (int r = 0; r < 4; r++) acc[t][r] = 0.f;

    #pragma unroll
    for (int kc = 0; kc < 8; kc++) {
        unsigned a[4];
        LDMX4(a[0], a[1], a[2], a[3], as_base +
            (uint32_t)(((wr + (lane & 15)) * AP + kc * 16 + (lane >> 4) * 8) * 2));
        #pragma unroll
        for (int t = 0; t < 2; t++) {
            unsigned b0, b1, b2, b3;
            LDMX4T(b0, b1, b2, b3, bs_base +
                (uint32_t)(((kc * 16 + (lane & 15)) * BP + wh * 32 + t * 16 + (lane >> 4) * 8) * 2));
            MMA16816(acc[2 * t],     a, b0, b1);
            MMA16816(acc[2 * t + 1], a, b2, b3);
        }
    }

    #pragma unroll
    for (int t = 0; t < 4; t++) {
        int e = nc * 64 + wh * 32 + t * 8 + q2;
        float2 bv = *(const float2*)&bias[e];
        #pragma unroll
        for (int half_ = 0; half_ < 2; half_++) {
            int m = mt * 64 + wr + g + half_ * 8;
            *(float2*)&out[m * 128 + e] =
                make_float2(acc[t][half_ * 2] + bv.x, acc[t][half_ * 2 + 1] + bv.y);
        }
    }
}

// =====================================================================
extern "C" void kernel_launch(void* const* d_in, const int* in_sizes, int n_in,
                              void* d_out, int out_size)
{
    const float* x     = (const float*)d_in[0];   // [4,4096,128]
    const float* Wqkv  = (const float*)d_in[1];   // [128,384]
    const float* Wout  = (const float*)d_in[2];   // [128,128]
    const float* bout  = (const float*)d_in[3];   // [128]
    float* out = (float*)d_out;                   // [4,4096,128]

    gemm_qkv_h<<<256, 256>>>(x, Wqkv);
    flash_kernel<<<dim3(32, 16), 256>>>();
    gemm_out_h<<<dim3(2, 256), 256>>>(Wout, bout, out);
}